// round 1
// baseline (speedup 1.0000x reference)
#include <cuda_runtime.h>
#include <math.h>

// Problem constants
#define NB   4
#define TSEQ 2048
#define CDIM 1024
#define NH   16
#define DHD  64
#define TOK  (NB * TSEQ)     // 8192 token rows
#define FDIM (4 * CDIM)      // 4096

// ---------------------------------------------------------------------------
// Scratch (static device globals; allocation-free per harness rules)
// ---------------------------------------------------------------------------
__device__ float g_h   [TOK * CDIM];   // LN1 output
__device__ float g_q   [TOK * CDIM];
__device__ float g_k   [TOK * CDIM];
__device__ float g_v   [TOK * CDIM];
__device__ float g_attn[TOK * CDIM];
__device__ float g_xmid[TOK * CDIM];   // x + attn proj
__device__ float g_h2  [TOK * CDIM];   // LN2 output
__device__ float g_ff  [TOK * FDIM];   // relu(h2 @ W1 + b1)

// ---------------------------------------------------------------------------
// LayerNorm: one block per row, 256 threads, C=1024 (4 floats/thread)
// ---------------------------------------------------------------------------
__global__ __launch_bounds__(256) void ln_kernel(
    const float* __restrict__ x, const float* __restrict__ g,
    const float* __restrict__ b, float* __restrict__ out)
{
    int row = blockIdx.x;
    int t = threadIdx.x;
    const float4* xr = reinterpret_cast<const float4*>(x + (size_t)row * CDIM);
    float4 v = xr[t];
    float s  = v.x + v.y + v.z + v.w;
    float ss = v.x * v.x + v.y * v.y + v.z * v.z + v.w * v.w;
    #pragma unroll
    for (int o = 16; o > 0; o >>= 1) {
        s  += __shfl_xor_sync(0xffffffffu, s,  o);
        ss += __shfl_xor_sync(0xffffffffu, ss, o);
    }
    __shared__ float sm1[8], sm2[8];
    int w = t >> 5, l = t & 31;
    if (l == 0) { sm1[w] = s; sm2[w] = ss; }
    __syncthreads();
    if (w == 0) {
        s  = (l < 8) ? sm1[l] : 0.f;
        ss = (l < 8) ? sm2[l] : 0.f;
        #pragma unroll
        for (int o = 4; o > 0; o >>= 1) {
            s  += __shfl_xor_sync(0xffffffffu, s,  o);
            ss += __shfl_xor_sync(0xffffffffu, ss, o);
        }
        if (l == 0) { sm1[0] = s; sm2[0] = ss; }
    }
    __syncthreads();
    float mu   = sm1[0] * (1.0f / CDIM);
    float var  = sm2[0] * (1.0f / CDIM) - mu * mu;
    float rstd = rsqrtf(var + 1e-5f);
    float4 gv = reinterpret_cast<const float4*>(g)[t];
    float4 bv = reinterpret_cast<const float4*>(b)[t];
    float4 o4;
    o4.x = (v.x - mu) * rstd * gv.x + bv.x;
    o4.y = (v.y - mu) * rstd * gv.y + bv.y;
    o4.z = (v.z - mu) * rstd * gv.z + bv.z;
    o4.w = (v.w - mu) * rstd * gv.w + bv.w;
    reinterpret_cast<float4*>(out + (size_t)row * CDIM)[t] = o4;
}

// ---------------------------------------------------------------------------
// SGEMM: C = A[M,K] @ B[K,N] (+bias)(relu)(+res). 128x128x8 tile, 8x8/thread.
// M,N multiples of 128; K multiple of 8.
// ---------------------------------------------------------------------------
template <bool BIAS, bool RELU, bool RES>
__global__ __launch_bounds__(256) void sgemm_kernel(
    const float* __restrict__ A, const float* __restrict__ B,
    const float* __restrict__ bias, const float* __restrict__ res,
    float* __restrict__ C, int M, int N, int K)
{
    const int BM = 128, BN = 128, BK = 8;
    __shared__ float As[BK][BM];
    __shared__ float Bs[BK][BN];
    int tid = threadIdx.x;
    int bm = blockIdx.y * BM;
    int bn = blockIdx.x * BN;

    int arow = tid >> 1;            // 0..127
    int acol = (tid & 1) * 4;       // 0 or 4
    int brow = tid >> 5;            // 0..7
    int bcol = (tid & 31) * 4;      // 0..124

    int ty = (tid >> 4) * 8;
    int tx = (tid & 15) * 8;

    float acc[8][8];
    #pragma unroll
    for (int i = 0; i < 8; i++)
        #pragma unroll
        for (int j = 0; j < 8; j++) acc[i][j] = 0.f;

    const float* Aptr = A + (size_t)(bm + arow) * K + acol;
    const float* Bptr = B + (size_t)brow * N + bn + bcol;

    for (int k0 = 0; k0 < K; k0 += BK) {
        float4 av = *reinterpret_cast<const float4*>(Aptr + k0);
        As[acol + 0][arow] = av.x;
        As[acol + 1][arow] = av.y;
        As[acol + 2][arow] = av.z;
        As[acol + 3][arow] = av.w;
        float4 bv = *reinterpret_cast<const float4*>(Bptr + (size_t)k0 * N);
        *reinterpret_cast<float4*>(&Bs[brow][bcol]) = bv;
        __syncthreads();
        #pragma unroll
        for (int k = 0; k < BK; k++) {
            float a[8], b[8];
            *reinterpret_cast<float4*>(a)     = *reinterpret_cast<float4*>(&As[k][ty]);
            *reinterpret_cast<float4*>(a + 4) = *reinterpret_cast<float4*>(&As[k][ty + 4]);
            *reinterpret_cast<float4*>(b)     = *reinterpret_cast<float4*>(&Bs[k][tx]);
            *reinterpret_cast<float4*>(b + 4) = *reinterpret_cast<float4*>(&Bs[k][tx + 4]);
            #pragma unroll
            for (int i = 0; i < 8; i++)
                #pragma unroll
                for (int j = 0; j < 8; j++)
                    acc[i][j] += a[i] * b[j];
        }
        __syncthreads();
    }

    #pragma unroll
    for (int i = 0; i < 8; i++) {
        int row = bm + ty + i;
        #pragma unroll
        for (int j = 0; j < 8; j += 4) {
            int col = bn + tx + j;
            float4 c;
            c.x = acc[i][j + 0]; c.y = acc[i][j + 1];
            c.z = acc[i][j + 2]; c.w = acc[i][j + 3];
            if (BIAS) {
                float4 bb = *reinterpret_cast<const float4*>(bias + col);
                c.x += bb.x; c.y += bb.y; c.z += bb.z; c.w += bb.w;
            }
            if (RELU) {
                c.x = fmaxf(c.x, 0.f); c.y = fmaxf(c.y, 0.f);
                c.z = fmaxf(c.z, 0.f); c.w = fmaxf(c.w, 0.f);
            }
            if (RES) {
                float4 r = *reinterpret_cast<const float4*>(res + (size_t)row * N + col);
                c.x += r.x; c.y += r.y; c.z += r.z; c.w += r.w;
            }
            *reinterpret_cast<float4*>(C + (size_t)row * N + col) = c;
        }
    }
}

// ---------------------------------------------------------------------------
// Flash attention (fp32): 64x64 tiles, online softmax, causal.
// grid = (T/64, H, B), block = 256 (16x16 threads, 4x4 micro-tile of S/O).
// q,k,v layout: [B*T, C] with column = h*64 + d.
// Dynamic smem: Qs[64][64], Kst[64][65] (transposed), Vs[64][65], Ps[64][65]
// ---------------------------------------------------------------------------
__global__ __launch_bounds__(256) void attn_kernel(
    const float* __restrict__ Q, const float* __restrict__ Kx,
    const float* __restrict__ Vx, float* __restrict__ O)
{
    extern __shared__ float smem[];
    float* Qs  = smem;              // [64][64]
    float* Kst = Qs + 64 * 64;      // [64][65] (d-major)
    float* Vs  = Kst + 64 * 65;     // [64][65] (n-major)
    float* Ps  = Vs + 64 * 65;      // [64][65]

    int mt = blockIdx.x, h = blockIdx.y, b = blockIdx.z;
    int tid = threadIdx.x;
    int ty = tid >> 4, tx = tid & 15;
    const float scale = 0.125f; // 1/sqrt(64)

    size_t base = (size_t)b * TSEQ * CDIM + (size_t)h * DHD;

    // load Q tile (scaled)
    #pragma unroll
    for (int i = 0; i < 16; i++) {
        int idx = tid + i * 256;
        int n = idx >> 6, d = idx & 63;
        Qs[n * 64 + d] = Q[base + (size_t)(mt * 64 + n) * CDIM + d] * scale;
    }

    float m[4], l[4], acc[4][4];
    #pragma unroll
    for (int i = 0; i < 4; i++) {
        m[i] = -1e30f; l[i] = 0.f;
        #pragma unroll
        for (int j = 0; j < 4; j++) acc[i][j] = 0.f;
    }
    __syncthreads();

    for (int nt = 0; nt <= mt; nt++) {
        // load K (transposed) and V tiles
        #pragma unroll
        for (int i = 0; i < 16; i++) {
            int idx = tid + i * 256;
            int n = idx >> 6, d = idx & 63;
            size_t g = base + (size_t)(nt * 64 + n) * CDIM + d;
            Kst[d * 65 + n] = Kx[g];
            Vs[n * 65 + d]  = Vx[g];
        }
        __syncthreads();

        // S = Q @ K^T  (4x4 per thread)
        float s[4][4];
        #pragma unroll
        for (int i = 0; i < 4; i++)
            #pragma unroll
            for (int j = 0; j < 4; j++) s[i][j] = 0.f;

        #pragma unroll 4
        for (int d = 0; d < 64; d++) {
            float a0 = Qs[(ty * 4 + 0) * 64 + d];
            float a1 = Qs[(ty * 4 + 1) * 64 + d];
            float a2 = Qs[(ty * 4 + 2) * 64 + d];
            float a3 = Qs[(ty * 4 + 3) * 64 + d];
            float b0 = Kst[d * 65 + tx * 4 + 0];
            float b1 = Kst[d * 65 + tx * 4 + 1];
            float b2 = Kst[d * 65 + tx * 4 + 2];
            float b3 = Kst[d * 65 + tx * 4 + 3];
            s[0][0] += a0 * b0; s[0][1] += a0 * b1; s[0][2] += a0 * b2; s[0][3] += a0 * b3;
            s[1][0] += a1 * b0; s[1][1] += a1 * b1; s[1][2] += a1 * b2; s[1][3] += a1 * b3;
            s[2][0] += a2 * b0; s[2][1] += a2 * b1; s[2][2] += a2 * b2; s[2][3] += a2 * b3;
            s[3][0] += a3 * b0; s[3][1] += a3 * b1; s[3][2] += a3 * b2; s[3][3] += a3 * b3;
        }

        // causal mask on the diagonal tile
        if (nt == mt) {
            #pragma unroll
            for (int i = 0; i < 4; i++)
                #pragma unroll
                for (int j = 0; j < 4; j++)
                    if (tx * 4 + j > ty * 4 + i) s[i][j] = -1e30f;
        }

        // online softmax per row (reduce across the 16-lane tx group)
        #pragma unroll
        for (int i = 0; i < 4; i++) {
            float rm = fmaxf(fmaxf(s[i][0], s[i][1]), fmaxf(s[i][2], s[i][3]));
            #pragma unroll
            for (int o = 8; o > 0; o >>= 1)
                rm = fmaxf(rm, __shfl_xor_sync(0xffffffffu, rm, o, 16));
            float mn = fmaxf(m[i], rm);
            float corr = __expf(m[i] - mn);
            l[i] *= corr;
            #pragma unroll
            for (int j = 0; j < 4; j++) acc[i][j] *= corr;
            float rs = 0.f;
            #pragma unroll
            for (int j = 0; j < 4; j++) {
                s[i][j] = __expf(s[i][j] - mn);
                rs += s[i][j];
            }
            #pragma unroll
            for (int o = 8; o > 0; o >>= 1)
                rs += __shfl_xor_sync(0xffffffffu, rs, o, 16);
            l[i] += rs;
            m[i] = mn;
        }

        // stage P to smem
        #pragma unroll
        for (int i = 0; i < 4; i++)
            #pragma unroll
            for (int j = 0; j < 4; j++)
                Ps[(ty * 4 + i) * 65 + tx * 4 + j] = s[i][j];
        __syncthreads();

        // O += P @ V
        #pragma unroll 4
        for (int d0 = 0; d0 < 64; d0++) {
            float p0 = Ps[(ty * 4 + 0) * 65 + d0];
            float p1 = Ps[(ty * 4 + 1) * 65 + d0];
            float p2 = Ps[(ty * 4 + 2) * 65 + d0];
            float p3 = Ps[(ty * 4 + 3) * 65 + d0];
            float v0 = Vs[d0 * 65 + tx * 4 + 0];
            float v1 = Vs[d0 * 65 + tx * 4 + 1];
            float v2 = Vs[d0 * 65 + tx * 4 + 2];
            float v3 = Vs[d0 * 65 + tx * 4 + 3];
            acc[0][0] += p0 * v0; acc[0][1] += p0 * v1; acc[0][2] += p0 * v2; acc[0][3] += p0 * v3;
            acc[1][0] += p1 * v0; acc[1][1] += p1 * v1; acc[1][2] += p1 * v2; acc[1][3] += p1 * v3;
            acc[2][0] += p2 * v0; acc[2][1] += p2 * v1; acc[2][2] += p2 * v2; acc[2][3] += p2 * v3;
            acc[3][0] += p3 * v0; acc[3][1] += p3 * v1; acc[3][2] += p3 * v2; acc[3][3] += p3 * v3;
        }
        __syncthreads();
    }

    // normalize and store (heads concatenated: col = h*64 + d)
    #pragma unroll
    for (int i = 0; i < 4; i++) {
        float inv = 1.0f / l[i];
        size_t off = base + (size_t)(mt * 64 + ty * 4 + i) * CDIM + tx * 4;
        float4 o4;
        o4.x = acc[i][0] * inv; o4.y = acc[i][1] * inv;
        o4.z = acc[i][2] * inv; o4.w = acc[i][3] * inv;
        *reinterpret_cast<float4*>(&O[off]) = o4;
    }
}

// ---------------------------------------------------------------------------
// Launch
// ---------------------------------------------------------------------------
extern "C" void kernel_launch(void* const* d_in, const int* in_sizes, int n_in,
                              void* d_out, int out_size)
{
    const float* x   = (const float*)d_in[0];
    const float* Wq  = (const float*)d_in[1];
    const float* Wk  = (const float*)d_in[2];
    const float* Wv  = (const float*)d_in[3];
    const float* Wp  = (const float*)d_in[4];
    const float* bp  = (const float*)d_in[5];
    const float* W1  = (const float*)d_in[6];
    const float* b1  = (const float*)d_in[7];
    const float* W2  = (const float*)d_in[8];
    const float* b2  = (const float*)d_in[9];
    const float* g1  = (const float*)d_in[10];
    const float* be1 = (const float*)d_in[11];
    const float* g2  = (const float*)d_in[12];
    const float* be2 = (const float*)d_in[13];
    float* out = (float*)d_out;

    float *h_, *q_, *k_, *v_, *at_, *xm_, *h2_, *ff_;
    cudaGetSymbolAddress((void**)&h_,  g_h);
    cudaGetSymbolAddress((void**)&q_,  g_q);
    cudaGetSymbolAddress((void**)&k_,  g_k);
    cudaGetSymbolAddress((void**)&v_,  g_v);
    cudaGetSymbolAddress((void**)&at_, g_attn);
    cudaGetSymbolAddress((void**)&xm_, g_xmid);
    cudaGetSymbolAddress((void**)&h2_, g_h2);
    cudaGetSymbolAddress((void**)&ff_, g_ff);

    // attention smem: Qs(4096) + Kst(4160) + Vs(4160) + Ps(4160) floats
    size_t attn_smem = (size_t)(64 * 64 + 3 * 64 * 65) * sizeof(float);
    static bool attr_set = false;
    if (!attr_set) {
        cudaFuncSetAttribute(attn_kernel,
                             cudaFuncAttributeMaxDynamicSharedMemorySize,
                             (int)attn_smem);
        attr_set = true;
    }

    dim3 blk(256);
    dim3 grid_c(CDIM / 128, TOK / 128);   // N=1024 GEMMs
    dim3 grid_f(FDIM / 128, TOK / 128);   // N=4096 GEMM
    dim3 grid_a(TSEQ / 64, NH, NB);

    // 1) LN1
    ln_kernel<<<TOK, 256>>>(x, g1, be1, h_);
    // 2-4) QKV projections
    sgemm_kernel<false, false, false><<<grid_c, blk>>>(h_, Wq, nullptr, nullptr, q_, TOK, CDIM, CDIM);
    sgemm_kernel<false, false, false><<<grid_c, blk>>>(h_, Wk, nullptr, nullptr, k_, TOK, CDIM, CDIM);
    sgemm_kernel<false, false, false><<<grid_c, blk>>>(h_, Wv, nullptr, nullptr, v_, TOK, CDIM, CDIM);
    // 5) causal flash attention
    attn_kernel<<<grid_a, blk, attn_smem>>>(q_, k_, v_, at_);
    // 6) output projection + bias + residual(x)
    sgemm_kernel<true, false, true><<<grid_c, blk>>>(at_, Wp, bp, x, xm_, TOK, CDIM, CDIM);
    // 7) LN2
    ln_kernel<<<TOK, 256>>>(xm_, g2, be2, h2_);
    // 8) FFN up + relu
    sgemm_kernel<true, true, false><<<grid_f, blk>>>(h2_, W1, b1, nullptr, ff_, TOK, FDIM, CDIM);
    // 9) FFN down + bias + residual(xmid) -> out
    sgemm_kernel<true, false, true><<<grid_c, blk>>>(ff_, W2, b2, xm_, out, TOK, CDIM, FDIM);
}

// round 9
// speedup vs baseline: 2.2454x; 2.2454x over previous
#include <cuda_runtime.h>
#include <math.h>

// Problem constants
#define NB   4
#define TSEQ 2048
#define CDIM 1024
#define NH   16
#define DHD  64
#define TOK  (NB * TSEQ)     // 8192 token rows
#define FDIM (4 * CDIM)      // 4096

// ---------------------------------------------------------------------------
// Scratch (static device globals; allocation-free per harness rules)
// ---------------------------------------------------------------------------
__device__ float g_h   [TOK * CDIM];
__device__ float g_q   [TOK * CDIM];
__device__ float g_k   [TOK * CDIM];
__device__ float g_v   [TOK * CDIM];
__device__ float g_attn[TOK * CDIM];
__device__ float g_xmid[TOK * CDIM];
__device__ float g_h2  [TOK * CDIM];
__device__ float g_ff  [TOK * FDIM];

// ---------------------------------------------------------------------------
// LayerNorm: one block per row, 256 threads, C=1024 (4 floats/thread)
// ---------------------------------------------------------------------------
__global__ __launch_bounds__(256) void ln_kernel(
    const float* __restrict__ x, const float* __restrict__ g,
    const float* __restrict__ b, float* __restrict__ out)
{
    int row = blockIdx.x;
    int t = threadIdx.x;
    const float4* xr = reinterpret_cast<const float4*>(x + (size_t)row * CDIM);
    float4 v = xr[t];
    float s  = v.x + v.y + v.z + v.w;
    float ss = v.x * v.x + v.y * v.y + v.z * v.z + v.w * v.w;
    #pragma unroll
    for (int o = 16; o > 0; o >>= 1) {
        s  += __shfl_xor_sync(0xffffffffu, s,  o);
        ss += __shfl_xor_sync(0xffffffffu, ss, o);
    }
    __shared__ float sm1[8], sm2[8];
    int w = t >> 5, l = t & 31;
    if (l == 0) { sm1[w] = s; sm2[w] = ss; }
    __syncthreads();
    if (w == 0) {
        s  = (l < 8) ? sm1[l] : 0.f;
        ss = (l < 8) ? sm2[l] : 0.f;
        #pragma unroll
        for (int o = 4; o > 0; o >>= 1) {
            s  += __shfl_xor_sync(0xffffffffu, s,  o);
            ss += __shfl_xor_sync(0xffffffffu, ss, o);
        }
        if (l == 0) { sm1[0] = s; sm2[0] = ss; }
    }
    __syncthreads();
    float mu   = sm1[0] * (1.0f / CDIM);
    float var  = sm2[0] * (1.0f / CDIM) - mu * mu;
    float rstd = rsqrtf(var + 1e-5f);
    float4 gv = reinterpret_cast<const float4*>(g)[t];
    float4 bv = reinterpret_cast<const float4*>(b)[t];
    float4 o4;
    o4.x = (v.x - mu) * rstd * gv.x + bv.x;
    o4.y = (v.y - mu) * rstd * gv.y + bv.y;
    o4.z = (v.z - mu) * rstd * gv.z + bv.z;
    o4.w = (v.w - mu) * rstd * gv.w + bv.w;
    reinterpret_cast<float4*>(out + (size_t)row * CDIM)[t] = o4;
}

// ---------------------------------------------------------------------------
// TF32 tensor-core GEMM: C = A[M,K] @ B[K,N] (+bias)(relu)(+res)
// 128x128x32 tile, 8 warps (4x2), warp tile 32x64, mma.m16n8k8 tf32.
// 3-stage cp.async pipeline. Smem strides chosen for conflict-free LDS:
//   A: [128][36] (bank = 4g+tg, distinct), B: [32][136] (bank = 8tg+g, distinct)
// ---------------------------------------------------------------------------
#define GBM 128
#define GBN 128
#define GBK 32
#define ASTR 36
#define BSTR 136
#define STAGE_A (GBM * ASTR)             // 4608 floats
#define STAGE_B (GBK * BSTR)             // 4352 floats
#define STAGE_F (STAGE_A + STAGE_B)      // 8960 floats
#define GEMM_SMEM (3 * STAGE_F * 4)      // 107520 bytes

#define CP_ASYNC16(dst, src) \
    asm volatile("cp.async.cg.shared.global [%0], [%1], 16;\n" :: "r"(dst), "l"(src))
#define CP_COMMIT() asm volatile("cp.async.commit_group;\n")
#define CP_WAIT1()  asm volatile("cp.async.wait_group 1;\n")
#define CP_WAIT0()  asm volatile("cp.async.wait_group 0;\n")

__device__ __forceinline__ unsigned f2tf32(float v) {
    unsigned r;
    asm("cvt.rna.tf32.f32 %0, %1;" : "=r"(r) : "f"(v));
    return r;
}

template <bool BIAS, bool RELU, bool RES>
__global__ __launch_bounds__(256) void gemm_tf32(
    const float* __restrict__ A, const float* __restrict__ B,
    const float* __restrict__ bias, const float* __restrict__ res,
    float* __restrict__ C, int M, int N, int K)
{
    extern __shared__ float smem[];
    const int tid  = threadIdx.x;
    const int lane = tid & 31;
    const int warp = tid >> 5;
    const int wm = (warp >> 1) * 32;    // warp M offset within tile
    const int wn = (warp & 1) * 64;     // warp N offset within tile
    const int g  = lane >> 2;           // 0..7
    const int tg = lane & 3;            // 0..3

    const int bm = blockIdx.y * GBM;
    const int bn = blockIdx.x * GBN;
    const unsigned sbase = (unsigned)__cvta_generic_to_shared(smem);

    float acc[2][8][4];
    #pragma unroll
    for (int mt = 0; mt < 2; mt++)
        #pragma unroll
        for (int nt = 0; nt < 8; nt++)
            #pragma unroll
            for (int i = 0; i < 4; i++) acc[mt][nt][i] = 0.f;

    const int NIT = K / GBK;

    // per-thread load coordinates (16B granules)
    // A tile: 128 rows x 8 f4; B tile: 32 rows x 32 f4; 1024 f4 each, 4/thread
    auto load_tiles = [&](int it, int stage) {
        int k0 = it * GBK;
        unsigned abase = sbase + (unsigned)(stage * STAGE_F) * 4u;
        unsigned bbase = abase + (unsigned)STAGE_A * 4u;
        #pragma unroll
        for (int i = 0; i < 4; i++) {
            int idx = tid + i * 256;
            int row = idx >> 3, c4 = idx & 7;
            unsigned dst = abase + (unsigned)(row * ASTR + c4 * 4) * 4u;
            const float* src = A + (size_t)(bm + row) * K + k0 + c4 * 4;
            CP_ASYNC16(dst, src);
        }
        #pragma unroll
        for (int i = 0; i < 4; i++) {
            int idx = tid + i * 256;
            int row = idx >> 5, c4 = idx & 31;
            unsigned dst = bbase + (unsigned)(row * BSTR + c4 * 4) * 4u;
            const float* src = B + (size_t)(k0 + row) * N + bn + c4 * 4;
            CP_ASYNC16(dst, src);
        }
    };

    // prologue: stages for it=0,1
    load_tiles(0, 0); CP_COMMIT();
    load_tiles(1, 1); CP_COMMIT();

    for (int it = 0; it < NIT; it++) {
        CP_WAIT1();
        __syncthreads();
        if (it + 2 < NIT) load_tiles(it + 2, (it + 2) % 3);
        CP_COMMIT();

        const float* As = smem + (it % 3) * STAGE_F;
        const float* Bs = As + STAGE_A;

        #pragma unroll
        for (int kc = 0; kc < GBK; kc += 8) {
            unsigned af[2][4];
            #pragma unroll
            for (int mt = 0; mt < 2; mt++) {
                const float* ap = As + (wm + mt * 16 + g) * ASTR + kc + tg;
                af[mt][0] = f2tf32(ap[0]);
                af[mt][1] = f2tf32(ap[8 * ASTR]);
                af[mt][2] = f2tf32(ap[4]);
                af[mt][3] = f2tf32(ap[8 * ASTR + 4]);
            }
            unsigned bf[8][2];
            #pragma unroll
            for (int nt = 0; nt < 8; nt++) {
                const float* bp = Bs + (kc + tg) * BSTR + wn + nt * 8 + g;
                bf[nt][0] = f2tf32(bp[0]);
                bf[nt][1] = f2tf32(bp[4 * BSTR]);
            }
            #pragma unroll
            for (int mt = 0; mt < 2; mt++)
                #pragma unroll
                for (int nt = 0; nt < 8; nt++) {
                    float* c = acc[mt][nt];
                    asm volatile(
                        "mma.sync.aligned.m16n8k8.row.col.f32.tf32.tf32.f32 "
                        "{%0,%1,%2,%3},{%4,%5,%6,%7},{%8,%9},{%0,%1,%2,%3};"
                        : "+f"(c[0]), "+f"(c[1]), "+f"(c[2]), "+f"(c[3])
                        : "r"(af[mt][0]), "r"(af[mt][1]), "r"(af[mt][2]), "r"(af[mt][3]),
                          "r"(bf[nt][0]), "r"(bf[nt][1]));
                }
        }
        __syncthreads();
    }
    CP_WAIT0();

    // epilogue
    #pragma unroll
    for (int mt = 0; mt < 2; mt++) {
        #pragma unroll
        for (int nt = 0; nt < 8; nt++) {
            float* c = acc[mt][nt];
            int row0 = bm + wm + mt * 16 + g;
            int col  = bn + wn + nt * 8 + tg * 2;
            float2 v0 = make_float2(c[0], c[1]);
            float2 v1 = make_float2(c[2], c[3]);
            if (BIAS) {
                float2 bb = *reinterpret_cast<const float2*>(bias + col);
                v0.x += bb.x; v0.y += bb.y;
                v1.x += bb.x; v1.y += bb.y;
            }
            if (RELU) {
                v0.x = fmaxf(v0.x, 0.f); v0.y = fmaxf(v0.y, 0.f);
                v1.x = fmaxf(v1.x, 0.f); v1.y = fmaxf(v1.y, 0.f);
            }
            if (RES) {
                float2 r0 = *reinterpret_cast<const float2*>(res + (size_t)row0 * N + col);
                float2 r1 = *reinterpret_cast<const float2*>(res + (size_t)(row0 + 8) * N + col);
                v0.x += r0.x; v0.y += r0.y;
                v1.x += r1.x; v1.y += r1.y;
            }
            *reinterpret_cast<float2*>(C + (size_t)row0 * N + col)       = v0;
            *reinterpret_cast<float2*>(C + (size_t)(row0 + 8) * N + col) = v1;
        }
    }
}

// ---------------------------------------------------------------------------
// Flash attention (fp32): 64x64 tiles, online softmax, causal.
// ---------------------------------------------------------------------------
__global__ __launch_bounds__(256) void attn_kernel(
    const float* __restrict__ Q, const float* __restrict__ Kx,
    const float* __restrict__ Vx, float* __restrict__ O)
{
    extern __shared__ float smem[];
    float* Qs  = smem;
    float* Kst = Qs + 64 * 64;
    float* Vs  = Kst + 64 * 65;
    float* Ps  = Vs + 64 * 65;

    int mt = blockIdx.x, h = blockIdx.y, b = blockIdx.z;
    int tid = threadIdx.x;
    int ty = tid >> 4, tx = tid & 15;
    const float scale = 0.125f;

    size_t base = (size_t)b * TSEQ * CDIM + (size_t)h * DHD;

    #pragma unroll
    for (int i = 0; i < 16; i++) {
        int idx = tid + i * 256;
        int n = idx >> 6, d = idx & 63;
        Qs[n * 64 + d] = Q[base + (size_t)(mt * 64 + n) * CDIM + d] * scale;
    }

    float m[4], l[4], acc[4][4];
    #pragma unroll
    for (int i = 0; i < 4; i++) {
        m[i] = -1e30f; l[i] = 0.f;
        #pragma unroll
        for (int j = 0; j < 4; j++) acc[i][j] = 0.f;
    }
    __syncthreads();

    for (int nt = 0; nt <= mt; nt++) {
        #pragma unroll
        for (int i = 0; i < 16; i++) {
            int idx = tid + i * 256;
            int n = idx >> 6, d = idx & 63;
            size_t gg = base + (size_t)(nt * 64 + n) * CDIM + d;
            Kst[d * 65 + n] = Kx[gg];
            Vs[n * 65 + d]  = Vx[gg];
        }
        __syncthreads();

        float s[4][4];
        #pragma unroll
        for (int i = 0; i < 4; i++)
            #pragma unroll
            for (int j = 0; j < 4; j++) s[i][j] = 0.f;

        #pragma unroll 4
        for (int d = 0; d < 64; d++) {
            float a0 = Qs[(ty * 4 + 0) * 64 + d];
            float a1 = Qs[(ty * 4 + 1) * 64 + d];
            float a2 = Qs[(ty * 4 + 2) * 64 + d];
            float a3 = Qs[(ty * 4 + 3) * 64 + d];
            float b0 = Kst[d * 65 + tx * 4 + 0];
            float b1 = Kst[d * 65 + tx * 4 + 1];
            float b2 = Kst[d * 65 + tx * 4 + 2];
            float b3 = Kst[d * 65 + tx * 4 + 3];
            s[0][0] += a0 * b0; s[0][1] += a0 * b1; s[0][2] += a0 * b2; s[0][3] += a0 * b3;
            s[1][0] += a1 * b0; s[1][1] += a1 * b1; s[1][2] += a1 * b2; s[1][3] += a1 * b3;
            s[2][0] += a2 * b0; s[2][1] += a2 * b1; s[2][2] += a2 * b2; s[2][3] += a2 * b3;
            s[3][0] += a3 * b0; s[3][1] += a3 * b1; s[3][2] += a3 * b2; s[3][3] += a3 * b3;
        }

        if (nt == mt) {
            #pragma unroll
            for (int i = 0; i < 4; i++)
                #pragma unroll
                for (int j = 0; j < 4; j++)
                    if (tx * 4 + j > ty * 4 + i) s[i][j] = -1e30f;
        }

        #pragma unroll
        for (int i = 0; i < 4; i++) {
            float rm = fmaxf(fmaxf(s[i][0], s[i][1]), fmaxf(s[i][2], s[i][3]));
            #pragma unroll
            for (int o = 8; o > 0; o >>= 1)
                rm = fmaxf(rm, __shfl_xor_sync(0xffffffffu, rm, o, 16));
            float mn = fmaxf(m[i], rm);
            float corr = __expf(m[i] - mn);
            l[i] *= corr;
            #pragma unroll
            for (int j = 0; j < 4; j++) acc[i][j] *= corr;
            float rs = 0.f;
            #pragma unroll
            for (int j = 0; j < 4; j++) {
                s[i][j] = __expf(s[i][j] - mn);
                rs += s[i][j];
            }
            #pragma unroll
            for (int o = 8; o > 0; o >>= 1)
                rs += __shfl_xor_sync(0xffffffffu, rs, o, 16);
            l[i] += rs;
            m[i] = mn;
        }

        #pragma unroll
        for (int i = 0; i < 4; i++)
            #pragma unroll
            for (int j = 0; j < 4; j++)
                Ps[(ty * 4 + i) * 65 + tx * 4 + j] = s[i][j];
        __syncthreads();

        #pragma unroll 4
        for (int d0 = 0; d0 < 64; d0++) {
            float p0 = Ps[(ty * 4 + 0) * 65 + d0];
            float p1 = Ps[(ty * 4 + 1) * 65 + d0];
            float p2 = Ps[(ty * 4 + 2) * 65 + d0];
            float p3 = Ps[(ty * 4 + 3) * 65 + d0];
            float v0 = Vs[d0 * 65 + tx * 4 + 0];
            float v1 = Vs[d0 * 65 + tx * 4 + 1];
            float v2 = Vs[d0 * 65 + tx * 4 + 2];
            float v3 = Vs[d0 * 65 + tx * 4 + 3];
            acc[0][0] += p0 * v0; acc[0][1] += p0 * v1; acc[0][2] += p0 * v2; acc[0][3] += p0 * v3;
            acc[1][0] += p1 * v0; acc[1][1] += p1 * v1; acc[1][2] += p1 * v2; acc[1][3] += p1 * v3;
            acc[2][0] += p2 * v0; acc[2][1] += p2 * v1; acc[2][2] += p2 * v2; acc[2][3] += p2 * v3;
            acc[3][0] += p3 * v0; acc[3][1] += p3 * v1; acc[3][2] += p3 * v2; acc[3][3] += p3 * v3;
        }
        __syncthreads();
    }

    #pragma unroll
    for (int i = 0; i < 4; i++) {
        float inv = 1.0f / l[i];
        size_t off = base + (size_t)(mt * 64 + ty * 4 + i) * CDIM + tx * 4;
        float4 o4;
        o4.x = acc[i][0] * inv; o4.y = acc[i][1] * inv;
        o4.z = acc[i][2] * inv; o4.w = acc[i][3] * inv;
        *reinterpret_cast<float4*>(&O[off]) = o4;
    }
}

// ---------------------------------------------------------------------------
// Launch
// ---------------------------------------------------------------------------
extern "C" void kernel_launch(void* const* d_in, const int* in_sizes, int n_in,
                              void* d_out, int out_size)
{
    const float* x   = (const float*)d_in[0];
    const float* Wq  = (const float*)d_in[1];
    const float* Wk  = (const float*)d_in[2];
    const float* Wv  = (const float*)d_in[3];
    const float* Wp  = (const float*)d_in[4];
    const float* bp  = (const float*)d_in[5];
    const float* W1  = (const float*)d_in[6];
    const float* b1  = (const float*)d_in[7];
    const float* W2  = (const float*)d_in[8];
    const float* b2  = (const float*)d_in[9];
    const float* g1  = (const float*)d_in[10];
    const float* be1 = (const float*)d_in[11];
    const float* g2  = (const float*)d_in[12];
    const float* be2 = (const float*)d_in[13];
    float* out = (float*)d_out;

    float *h_, *q_, *k_, *v_, *at_, *xm_, *h2_, *ff_;
    cudaGetSymbolAddress((void**)&h_,  g_h);
    cudaGetSymbolAddress((void**)&q_,  g_q);
    cudaGetSymbolAddress((void**)&k_,  g_k);
    cudaGetSymbolAddress((void**)&v_,  g_v);
    cudaGetSymbolAddress((void**)&at_, g_attn);
    cudaGetSymbolAddress((void**)&xm_, g_xmid);
    cudaGetSymbolAddress((void**)&h2_, g_h2);
    cudaGetSymbolAddress((void**)&ff_, g_ff);

    size_t attn_smem = (size_t)(64 * 64 + 3 * 64 * 65) * sizeof(float);
    cudaFuncSetAttribute(attn_kernel,
                         cudaFuncAttributeMaxDynamicSharedMemorySize, (int)attn_smem);
    cudaFuncSetAttribute(gemm_tf32<false, false, false>,
                         cudaFuncAttributeMaxDynamicSharedMemorySize, GEMM_SMEM);
    cudaFuncSetAttribute(gemm_tf32<true, false, true>,
                         cudaFuncAttributeMaxDynamicSharedMemorySize, GEMM_SMEM);
    cudaFuncSetAttribute(gemm_tf32<true, true, false>,
                         cudaFuncAttributeMaxDynamicSharedMemorySize, GEMM_SMEM);

    dim3 blk(256);
    dim3 grid_c(CDIM / GBN, TOK / GBM);   // (8, 64)
    dim3 grid_f(FDIM / GBN, TOK / GBM);   // (32, 64)
    dim3 grid_a(TSEQ / 64, NH, NB);

    // 1) LN1
    ln_kernel<<<TOK, 256>>>(x, g1, be1, h_);
    // 2-4) QKV projections (tf32)
    gemm_tf32<false, false, false><<<grid_c, blk, GEMM_SMEM>>>(h_, Wq, nullptr, nullptr, q_, TOK, CDIM, CDIM);
    gemm_tf32<false, false, false><<<grid_c, blk, GEMM_SMEM>>>(h_, Wk, nullptr, nullptr, k_, TOK, CDIM, CDIM);
    gemm_tf32<false, false, false><<<grid_c, blk, GEMM_SMEM>>>(h_, Wv, nullptr, nullptr, v_, TOK, CDIM, CDIM);
    // 5) causal flash attention
    attn_kernel<<<grid_a, blk, attn_smem>>>(q_, k_, v_, at_);
    // 6) output projection + bias + residual(x)
    gemm_tf32<true, false, true><<<grid_c, blk, GEMM_SMEM>>>(at_, Wp, bp, x, xm_, TOK, CDIM, CDIM);
    // 7) LN2
    ln_kernel<<<TOK, 256>>>(xm_, g2, be2, h2_);
    // 8) FFN up + relu
    gemm_tf32<true, true, false><<<grid_f, blk, GEMM_SMEM>>>(h2_, W1, b1, nullptr, ff_, TOK, FDIM, CDIM);
    // 9) FFN down + bias + residual(xmid) -> out
    gemm_tf32<true, false, true><<<grid_c, blk, GEMM_SMEM>>>(ff_, W2, b2, xm_, out, TOK, CDIM, FDIM);
}